// round 1
// baseline (speedup 1.0000x reference)
#include <cuda_runtime.h>

#define BATCH   8
#define CH      2049          // N/2+1 spectrum bins
#define TFR     345           // frames
#define NFFT    4096
#define MH      2048          // NFFT/2
#define HOP     1024
#define NFRAMES (BATCH*TFR)   // 2760

// ---------------- scratch (device globals; no allocations) ----------------
__device__ float2 g_spec[NFRAMES * CH];     // [frame][k] = (Re, Im)   ~45.2 MB
__device__ float2 g_frames[NFRAMES * MH];   // [frame][m] = (x[2m], x[2m+1]) ~45.2 MB
__device__ float2 g_twN[MH];                // e^{+2*pi*i*k/4096}, k=0..2047
__device__ float2 g_win[MH];                // (hann[2m], hann[2m+1])

// ---------------- table init (cheap, re-run every launch: deterministic) ----
__global__ void init_tables()
{
    int i = blockIdx.x * blockDim.x + threadIdx.x;
    if (i < MH) {
        double ang = 6.283185307179586476925286766559 * (double)i / (double)NFFT;
        g_twN[i] = make_float2((float)cos(ang), (float)sin(ang));
        double a0 = 6.283185307179586476925286766559 * (double)(2*i)   / (double)NFFT;
        double a1 = 6.283185307179586476925286766559 * (double)(2*i+1) / (double)NFFT;
        g_win[i] = make_float2((float)(0.5 - 0.5*cos(a0)),
                               (float)(0.5 - 0.5*cos(a1)));
    }
}

// ---------------- transpose [B, CH, T] -> g_spec[(b*T+t)*CH + k] -----------
__global__ void transpose_kernel(const float* __restrict__ re,
                                 const float* __restrict__ im)
{
    __shared__ float sr[32][33];
    __shared__ float si[32][33];
    int b  = blockIdx.z;
    int k0 = blockIdx.x << 5, t0 = blockIdx.y << 5;
    int tx = threadIdx.x, ty = threadIdx.y;
    const float* rb = re + (size_t)b * CH * TFR;
    const float* ib = im + (size_t)b * CH * TFR;
    int k = k0 + ty, t = t0 + tx;
    if (k < CH && t < TFR) {
        sr[ty][tx] = rb[k * TFR + t];
        si[ty][tx] = ib[k * TFR + t];
    }
    __syncthreads();
    int ko = k0 + tx, to = t0 + ty;
    if (ko < CH && to < TFR)
        g_spec[((size_t)b * TFR + to) * CH + ko] =
            make_float2(sr[tx][ty], si[tx][ty]);
}

// ---------------- per-frame inverse real FFT (size 4096) -------------------
// Half-size packing: X[k] = (R_k + i I_k)/256 (imag zeroed at k=0,2048),
//   E[k] = X[k] + conj(X[M-k]);  D[k] = X[k] - conj(X[M-k])
//   Z[k] = E[k] + i * (D[k] * e^{+2*pi*i*k/N})
//   y    = unnormalized IDFT_M(Z)  (e^{+} twiddles)  -> x[2m]=Re y, x[2m+1]=Im y
// frames[n] = hann[n] * x[n]
__global__ void __launch_bounds__(256) ifft_kernel()
{
    __shared__ float2 bufA[MH];
    __shared__ float2 bufB[MH];
    __shared__ float2 tws[1024];   // e^{+2*pi*i*r/2048} = g_twN[2r]

    int f   = blockIdx.x;
    int tid = threadIdx.x;
    const float2* __restrict__ X = g_spec + (size_t)f * CH;

    for (int r = tid; r < 1024; r += 256) tws[r] = g_twN[2 * r];

    const float sc = 1.0f / 256.0f;
    for (int k = tid; k < MH; k += 256) {
        float2 Xk = X[k];
        float2 Xc = X[MH - k];
        if (k == 0) { Xk.y = 0.f; Xc.y = 0.f; }   // sin rows at k=0,2048 have zero scale
        float ex = sc * (Xk.x + Xc.x);
        float ey = sc * (Xk.y - Xc.y);
        float dx = sc * (Xk.x - Xc.x);
        float dy = sc * (Xk.y + Xc.y);
        float2 w = g_twN[k];
        float ox = dx * w.x - dy * w.y;
        float oy = dx * w.y + dy * w.x;
        bufA[k] = make_float2(ex - oy, ey + ox);
    }
    __syncthreads();

    // Radix-2 Stockham, 11 passes, e^{+} twiddles (self-sorting).
    float2* a = bufA;
    float2* b = bufB;
    #pragma unroll
    for (int s = 0; s < 11; s++) {
        int m = 1 << s;
        #pragma unroll
        for (int q = 0; q < 4; q++) {
            int idx = tid + (q << 8);             // 0..1023 butterflies
            float2 t0 = a[idx];
            float2 t1 = a[idx + 1024];
            int jm = idx & ~(m - 1);              // == (j<<s), twiddle row
            float2 w = tws[jm];
            int wr = idx + jm;
            b[wr] = make_float2(t0.x + t1.x, t0.y + t1.y);
            float dx = t0.x - t1.x, dy = t0.y - t1.y;
            b[wr + m] = make_float2(dx * w.x - dy * w.y,
                                    dx * w.y + dy * w.x);
        }
        __syncthreads();
        float2* tmp = a; a = b; b = tmp;
    }

    float2* fr = g_frames + (size_t)f * MH;
    for (int mm = tid; mm < MH; mm += 256) {
        float2 y = a[mm];
        float2 w = g_win[mm];
        fr[mm] = make_float2(y.x * w.x, y.y * w.y);
    }
}

// ---------------- gather overlap-add + window-sum normalization ------------
__global__ void ola_kernel(const float* __restrict__ wsi,
                           float* __restrict__ out, int outlen)
{
    int j = blockIdx.x * blockDim.x + threadIdx.x;
    int b = blockIdx.y;
    if (j >= outlen) return;
    int p = j + MH;                                // skip first N/2 samples
    int thi = min(TFR - 1, p >> 10);
    int tlo = max(0, (p - (NFFT - HOP)) >> 10);    // ceil((p-4095)/1024)
    const float* fr = (const float*)g_frames;
    float acc = 0.f;
    #pragma unroll 4
    for (int t = tlo; t <= thi; t++)
        acc += fr[((size_t)(b * TFR + t) << 12) + (p - (t << 10))];
    out[(size_t)b * outlen + j] = acc * wsi[p];
}

// ---------------- launch ----------------------------------------------------
extern "C" void kernel_launch(void* const* d_in, const int* in_sizes, int n_in,
                              void* d_out, int out_size)
{
    const float* re  = (const float*)d_in[0];
    const float* im  = (const float*)d_in[1];
    // d_in[2] = inverse_basis (unused: replaced analytically by the iFFT)
    const float* wsi = (const float*)d_in[3];
    float* out = (float*)d_out;
    int outlen = out_size / BATCH;   // 352800

    init_tables<<<(MH + 255) / 256, 256>>>();

    dim3 tgrid((CH + 31) / 32, (TFR + 31) / 32, BATCH);
    transpose_kernel<<<tgrid, dim3(32, 32)>>>(re, im);

    ifft_kernel<<<NFRAMES, 256>>>();

    ola_kernel<<<dim3((outlen + 255) / 256, BATCH), 256>>>(wsi, out, outlen);
}

// round 2
// speedup vs baseline: 1.5102x; 1.5102x over previous
#include <cuda_runtime.h>

#define BATCH   8
#define CH      2049          // N/2+1 spectrum bins
#define TFR     345           // frames
#define NFFT    4096
#define MH      2048          // NFFT/2 = complex FFT size
#define HOP     1024
#define NFRAMES (BATCH*TFR)   // 2760

// ---------------- scratch (device globals; no allocations) ----------------
__device__ float2 g_spec[NFRAMES * CH];     // [frame][k] = (Re, Im)
__device__ float2 g_frames[NFRAMES * MH];   // [frame][m] = (x[2m], x[2m+1])
__device__ float2 g_twN[MH];                // e^{+2*pi*i*k/4096}
__device__ float2 g_win[MH];                // (hann[2m], hann[2m+1])

// smem bank swizzle (float2 index granularity; 16 float2 = 128B row)
#define SW(p) ((p) ^ (((p) >> 4) & 15))

__device__ __forceinline__ float2 cmul(float2 a, float2 b) {
    return make_float2(a.x*b.x - a.y*b.y, a.x*b.y + a.y*b.x);
}
__device__ __forceinline__ float2 cadd(float2 a, float2 b){ return make_float2(a.x+b.x, a.y+b.y); }
__device__ __forceinline__ float2 csub(float2 a, float2 b){ return make_float2(a.x-b.x, a.y-b.y); }
__device__ __forceinline__ float2 cmuli(float2 a){ return make_float2(-a.y, a.x); }   // i*a

// ---------------- table init -------------------------------------------------
__global__ void init_tables()
{
    int i = blockIdx.x * blockDim.x + threadIdx.x;
    if (i < MH) {
        double ang = 6.283185307179586476925286766559 * (double)i / (double)NFFT;
        g_twN[i] = make_float2((float)cos(ang), (float)sin(ang));
        double a0 = 6.283185307179586476925286766559 * (double)(2*i)   / (double)NFFT;
        double a1 = 6.283185307179586476925286766559 * (double)(2*i+1) / (double)NFFT;
        g_win[i] = make_float2((float)(0.5 - 0.5*cos(a0)),
                               (float)(0.5 - 0.5*cos(a1)));
    }
}

// ---------------- transpose [B, CH, T] -> g_spec[(b*T+t)*CH + k] -------------
__global__ void transpose_kernel(const float* __restrict__ re,
                                 const float* __restrict__ im)
{
    __shared__ float sr[32][33];
    __shared__ float si[32][33];
    int b  = blockIdx.z;
    int k0 = blockIdx.x << 5, t0 = blockIdx.y << 5;
    int tx = threadIdx.x, ty = threadIdx.y;
    const float* rb = re + (size_t)b * CH * TFR;
    const float* ib = im + (size_t)b * CH * TFR;
    int k = k0 + ty, t = t0 + tx;
    if (k < CH && t < TFR) {
        sr[ty][tx] = rb[k * TFR + t];
        si[ty][tx] = ib[k * TFR + t];
    }
    __syncthreads();
    int ko = k0 + tx, to = t0 + ty;
    if (ko < CH && to < TFR)
        g_spec[((size_t)b * TFR + to) * CH + ko] =
            make_float2(sr[tx][ty], si[tx][ty]);
}

// ---------------- radix-8 Stockham DIF pass (inverse, e^{+}) -----------------
// 256 butterflies, one per thread. y_q = W_2048^{q*jm} * IDFT8_q(x),
// inputs a[idx + 256 q], outputs b[8*jm + i + q*m].
__device__ __forceinline__ void radix8_pass(const float2* __restrict__ a,
                                            float2* __restrict__ b,
                                            const float2* __restrict__ tws,
                                            int tid, int m)
{
    int i  = tid & (m - 1);
    int jm = tid - i;

    float2 x0 = a[SW(tid        )];
    float2 x1 = a[SW(tid +  256)];
    float2 x2 = a[SW(tid +  512)];
    float2 x3 = a[SW(tid +  768)];
    float2 x4 = a[SW(tid + 1024)];
    float2 x5 = a[SW(tid + 1280)];
    float2 x6 = a[SW(tid + 1536)];
    float2 x7 = a[SW(tid + 1792)];

    // even 4-IDFT of (x0,x2,x4,x6)
    float2 ta = cadd(x0, x4), tb = csub(x0, x4);
    float2 tc = cadd(x2, x6), td = cmuli(csub(x2, x6));
    float2 E0 = cadd(ta, tc), E1 = cadd(tb, td);
    float2 E2 = csub(ta, tc), E3 = csub(tb, td);
    // odd 4-IDFT of (x1,x3,x5,x7)
    float2 sa = cadd(x1, x5), sb = csub(x1, x5);
    float2 sc = cadd(x3, x7), sd = cmuli(csub(x3, x7));
    float2 O0 = cadd(sa, sc), O1 = cadd(sb, sd);
    float2 O2 = csub(sa, sc), O3 = csub(sb, sd);
    // * w8^q, w8 = e^{+i pi/4}
    const float R = 0.70710678118654752440f;
    O1 = make_float2(R*(O1.x - O1.y), R*(O1.x + O1.y));
    O2 = cmuli(O2);
    O3 = make_float2(R*(-O3.x - O3.y), R*(O3.x - O3.y));

    float2 y0 = cadd(E0, O0), y4 = csub(E0, O0);
    float2 y1 = cadd(E1, O1), y5 = csub(E1, O1);
    float2 y2 = cadd(E2, O2), y6 = csub(E2, O2);
    float2 y3 = cadd(E3, O3), y7 = csub(E3, O3);

    float2 w1 = tws[jm];
    float2 w2 = cmul(w1, w1);
    float2 w3 = cmul(w2, w1);
    float2 w4 = cmul(w2, w2);
    float2 w5 = cmul(w4, w1);
    float2 w6 = cmul(w4, w2);
    float2 w7 = cmul(w4, w3);

    int base = tid + 7 * jm;          // = 8*jm + i
    b[SW(base      )] = y0;
    b[SW(base +   m)] = cmul(y1, w1);
    b[SW(base + 2*m)] = cmul(y2, w2);
    b[SW(base + 3*m)] = cmul(y3, w3);
    b[SW(base + 4*m)] = cmul(y4, w4);
    b[SW(base + 5*m)] = cmul(y5, w5);
    b[SW(base + 6*m)] = cmul(y6, w6);
    b[SW(base + 7*m)] = cmul(y7, w7);
}

// ---------------- per-frame inverse real FFT (size 4096) ---------------------
__global__ void __launch_bounds__(256) ifft_kernel()
{
    __shared__ float2 bufA[MH];
    __shared__ float2 bufB[MH];
    __shared__ float2 tws[256];   // W_2048^r, r in [0,256)

    int f   = blockIdx.x;
    int tid = threadIdx.x;
    const float2* __restrict__ X = g_spec + (size_t)f * CH;

    tws[tid] = g_twN[2 * tid];

    // pack: Z[k] = E[k] + i * W_4096^k * D[k]  (half-size real-IFFT packing)
    const float sc = 1.0f / 256.0f;
    #pragma unroll
    for (int j = 0; j < 8; j++) {
        int k = tid + (j << 8);
        float2 Xk = X[k];
        float2 Xc = X[MH - k];
        if (k == 0) { Xk.y = 0.f; Xc.y = 0.f; }
        float ex = sc * (Xk.x + Xc.x);
        float ey = sc * (Xk.y - Xc.y);
        float dx = sc * (Xk.x - Xc.x);
        float dy = sc * (Xk.y + Xc.y);
        float2 w = g_twN[k];
        float ox = dx * w.x - dy * w.y;
        float oy = dx * w.y + dy * w.x;
        bufA[SW(k)] = make_float2(ex - oy, ey + ox);
    }
    __syncthreads();

    radix8_pass(bufA, bufB, tws, tid, 1);
    __syncthreads();
    radix8_pass(bufB, bufA, tws, tid, 8);
    __syncthreads();
    radix8_pass(bufA, bufB, tws, tid, 64);
    __syncthreads();

    // final radix-4 pass (m=512, jm=0 -> twiddle-free) fused with window+store
    float2* __restrict__ fr = g_frames + (size_t)f * MH;
    #pragma unroll
    for (int j = 0; j < 2; j++) {
        int p = tid + (j << 8);                     // butterfly index in [0,512)
        float2 x0 = bufB[SW(p       )];
        float2 x1 = bufB[SW(p +  512)];
        float2 x2 = bufB[SW(p + 1024)];
        float2 x3 = bufB[SW(p + 1536)];
        float2 e = cadd(x0, x2), o = cadd(x1, x3);
        float2 em = csub(x0, x2), om = cmuli(csub(x1, x3));
        float2 y0 = cadd(e, o);          // n = p
        float2 y1 = cadd(em, om);        // n = p + 512
        float2 y2 = csub(e, o);          // n = p + 1024
        float2 y3 = csub(em, om);        // n = p + 1536
        float2 w;
        w = g_win[p       ]; fr[p       ] = make_float2(y0.x*w.x, y0.y*w.y);
        w = g_win[p +  512]; fr[p +  512] = make_float2(y1.x*w.x, y1.y*w.y);
        w = g_win[p + 1024]; fr[p + 1024] = make_float2(y2.x*w.x, y2.y*w.y);
        w = g_win[p + 1536]; fr[p + 1536] = make_float2(y3.x*w.x, y3.y*w.y);
    }
}

// ---------------- gather overlap-add, segment-structured, float4 -------------
__global__ void __launch_bounds__(256) ola_kernel(const float* __restrict__ wsi,
                                                  float* __restrict__ out, int outlen)
{
    int s = blockIdx.x;                // 1024-sample output segment
    int b = blockIdx.y;
    int r = threadIdx.x << 2;          // 0..1020, float4 per thread
    int j = (s << 10) + r;
    if (j >= outlen) return;
    int p   = j + MH;                  // position in padded signal (skip N/2)
    int seg = p >> 10;                 // = s + 2
    const float* frbase = (const float*)g_frames + (size_t)b * TFR * NFFT;

    float4 acc = make_float4(0.f, 0.f, 0.f, 0.f);
    #pragma unroll
    for (int d = 0; d < 4; d++) {
        int t = seg - d;
        if (t >= 0 && t < TFR) {
            const float4 v = *(const float4*)(frbase + (size_t)t * NFFT + r + (d << 10));
            acc.x += v.x; acc.y += v.y; acc.z += v.z; acc.w += v.w;
        }
    }
    float4 wv = *(const float4*)(wsi + p);
    float4 o;
    o.x = acc.x * wv.x; o.y = acc.y * wv.y;
    o.z = acc.z * wv.z; o.w = acc.w * wv.w;
    *(float4*)(out + (size_t)b * outlen + j) = o;
}

// ---------------- launch -----------------------------------------------------
extern "C" void kernel_launch(void* const* d_in, const int* in_sizes, int n_in,
                              void* d_out, int out_size)
{
    const float* re  = (const float*)d_in[0];
    const float* im  = (const float*)d_in[1];
    // d_in[2] = inverse_basis (unused: replaced analytically by the iFFT)
    const float* wsi = (const float*)d_in[3];
    float* out = (float*)d_out;
    int outlen = out_size / BATCH;     // 352800

    init_tables<<<16, 128>>>();

    dim3 tgrid((CH + 31) / 32, (TFR + 31) / 32, BATCH);
    transpose_kernel<<<tgrid, dim3(32, 32)>>>(re, im);

    ifft_kernel<<<NFRAMES, 256>>>();

    ola_kernel<<<dim3((outlen + 1023) / 1024, BATCH), 256>>>(wsi, out, outlen);
}

// round 3
// speedup vs baseline: 1.7037x; 1.1281x over previous
#include <cuda_runtime.h>

#define BATCH   8
#define CH      2049          // N/2+1 spectrum bins
#define TFR     345           // frames
#define NFFT    4096
#define MH      2048          // NFFT/2 = complex FFT size
#define HOP     1024
#define NFRAMES (BATCH*TFR)   // 2760

// ---------------- scratch (device globals; no allocations) ----------------
__device__ float2 g_spec[NFRAMES * CH];     // [frame][k] = (Re, Im)
__device__ float2 g_frames[NFRAMES * MH];   // [frame][m] = (x[2m], x[2m+1])
__device__ float2 g_twN[MH];                // e^{+2*pi*i*k/4096}
__device__ float2 g_win[MH];                // (hann[2m], hann[2m+1])

// smem bank swizzle (float2 index granularity; 16 float2 = 128B row)
#define SW(p) ((p) ^ (((p) >> 4) & 15))

__device__ __forceinline__ float2 cmul(float2 a, float2 b) {
    return make_float2(a.x*b.x - a.y*b.y, a.x*b.y + a.y*b.x);
}
__device__ __forceinline__ float2 cadd(float2 a, float2 b){ return make_float2(a.x+b.x, a.y+b.y); }
__device__ __forceinline__ float2 csub(float2 a, float2 b){ return make_float2(a.x-b.x, a.y-b.y); }
__device__ __forceinline__ float2 cmuli(float2 a){ return make_float2(-a.y, a.x); }   // i*a

// ---------------- transpose [B, CH, T] -> g_spec, with fused table init -----
__global__ void transpose_kernel(const float* __restrict__ re,
                                 const float* __restrict__ im)
{
    __shared__ float sr[32][33];
    __shared__ float si[32][33];
    int b  = blockIdx.z;
    int k0 = blockIdx.x << 5, t0 = blockIdx.y << 5;
    int tx = threadIdx.x, ty = threadIdx.y;

    // fused twiddle/window table init: first two (x,0,0) blocks cover 2048 ids
    if (blockIdx.y == 0 && blockIdx.z == 0 && blockIdx.x < 2) {
        int gid = (blockIdx.x << 10) + (ty << 5) + tx;
        if (gid < MH) {
            double ang = 6.283185307179586476925286766559 * (double)gid / (double)NFFT;
            g_twN[gid] = make_float2((float)cos(ang), (float)sin(ang));
            double a0 = 6.283185307179586476925286766559 * (double)(2*gid)   / (double)NFFT;
            double a1 = 6.283185307179586476925286766559 * (double)(2*gid+1) / (double)NFFT;
            g_win[gid] = make_float2((float)(0.5 - 0.5*cos(a0)),
                                     (float)(0.5 - 0.5*cos(a1)));
        }
    }

    const float* rb = re + (size_t)b * CH * TFR;
    const float* ib = im + (size_t)b * CH * TFR;
    int k = k0 + ty, t = t0 + tx;
    if (k < CH && t < TFR) {
        sr[ty][tx] = rb[k * TFR + t];
        si[ty][tx] = ib[k * TFR + t];
    }
    __syncthreads();
    int ko = k0 + tx, to = t0 + ty;
    if (ko < CH && to < TFR)
        g_spec[((size_t)b * TFR + to) * CH + ko] =
            make_float2(sr[tx][ty], si[tx][ty]);
}

// ---------------- in-place radix-8 Stockham DIF pass (inverse, e^{+}) -------
// 256 butterflies, one per thread; register staging + barriers make the
// in-place permutation safe. y_q = W_2048^{q*jm} * IDFT8_q(x).
__device__ __forceinline__ void radix8_pass_ip(float2* __restrict__ buf,
                                               const float2* __restrict__ tws,
                                               int tid, int m)
{
    int i  = tid & (m - 1);
    int jm = tid - i;

    float2 x0 = buf[SW(tid        )];
    float2 x1 = buf[SW(tid +  256)];
    float2 x2 = buf[SW(tid +  512)];
    float2 x3 = buf[SW(tid +  768)];
    float2 x4 = buf[SW(tid + 1024)];
    float2 x5 = buf[SW(tid + 1280)];
    float2 x6 = buf[SW(tid + 1536)];
    float2 x7 = buf[SW(tid + 1792)];
    float2 w1 = tws[jm];
    __syncthreads();

    // even 4-IDFT of (x0,x2,x4,x6)
    float2 ta = cadd(x0, x4), tb = csub(x0, x4);
    float2 tc = cadd(x2, x6), td = cmuli(csub(x2, x6));
    float2 E0 = cadd(ta, tc), E1 = cadd(tb, td);
    float2 E2 = csub(ta, tc), E3 = csub(tb, td);
    // odd 4-IDFT of (x1,x3,x5,x7)
    float2 sa = cadd(x1, x5), sb = csub(x1, x5);
    float2 sc = cadd(x3, x7), sd = cmuli(csub(x3, x7));
    float2 O0 = cadd(sa, sc), O1 = cadd(sb, sd);
    float2 O2 = csub(sa, sc), O3 = csub(sb, sd);
    // * w8^q, w8 = e^{+i pi/4}
    const float R = 0.70710678118654752440f;
    O1 = make_float2(R*(O1.x - O1.y), R*(O1.x + O1.y));
    O2 = cmuli(O2);
    O3 = make_float2(R*(-O3.x - O3.y), R*(O3.x - O3.y));

    float2 y0 = cadd(E0, O0), y4 = csub(E0, O0);
    float2 y1 = cadd(E1, O1), y5 = csub(E1, O1);
    float2 y2 = cadd(E2, O2), y6 = csub(E2, O2);
    float2 y3 = cadd(E3, O3), y7 = csub(E3, O3);

    // twiddle powers, shallow dependency tree
    float2 w2 = cmul(w1, w1);
    float2 w3 = cmul(w2, w1);
    float2 w4 = cmul(w2, w2);
    float2 w5 = cmul(w3, w2);
    float2 w6 = cmul(w3, w3);
    float2 w7 = cmul(w4, w3);

    int base = tid + 7 * jm;          // = 8*jm + i
    buf[SW(base      )] = y0;
    buf[SW(base +   m)] = cmul(y1, w1);
    buf[SW(base + 2*m)] = cmul(y2, w2);
    buf[SW(base + 3*m)] = cmul(y3, w3);
    buf[SW(base + 4*m)] = cmul(y4, w4);
    buf[SW(base + 5*m)] = cmul(y5, w5);
    buf[SW(base + 6*m)] = cmul(y6, w6);
    buf[SW(base + 7*m)] = cmul(y7, w7);
    __syncthreads();
}

// ---------------- per-frame inverse real FFT (size 4096) ---------------------
// Half-size packing: Z[k] = E[k] + i * W_4096^k * D[k]; y = IDFT_2048(Z);
// x[2m]=Re y[m], x[2m+1]=Im y[m]; frames[n] = hann[n]*x[n].
__global__ void __launch_bounds__(256) ifft_kernel()
{
    __shared__ float2 buf[MH];     // single in-place buffer (16 KB)
    __shared__ float2 tws[256];    // W_2048^r, r in [0,256)

    int f   = blockIdx.x;
    int tid = threadIdx.x;
    const float2* __restrict__ X = g_spec + (size_t)f * CH;

    tws[tid] = g_twN[2 * tid];

    const float sc = 1.0f / 256.0f;
    #pragma unroll
    for (int j = 0; j < 8; j++) {
        int k = tid + (j << 8);
        float2 Xk = X[k];
        float2 Xc = X[MH - k];
        if (k == 0) { Xk.y = 0.f; Xc.y = 0.f; }
        float ex = sc * (Xk.x + Xc.x);
        float ey = sc * (Xk.y - Xc.y);
        float dx = sc * (Xk.x - Xc.x);
        float dy = sc * (Xk.y + Xc.y);
        float2 w = g_twN[k];
        float ox = dx * w.x - dy * w.y;
        float oy = dx * w.y + dy * w.x;
        buf[SW(k)] = make_float2(ex - oy, ey + ox);
    }
    __syncthreads();

    radix8_pass_ip(buf, tws, tid, 1);
    radix8_pass_ip(buf, tws, tid, 8);
    radix8_pass_ip(buf, tws, tid, 64);

    // final radix-4 pass (m=512, jm=0 -> twiddle-free) fused with window+store
    float2* __restrict__ fr = g_frames + (size_t)f * MH;
    #pragma unroll
    for (int j = 0; j < 2; j++) {
        int p = tid + (j << 8);                     // butterfly index in [0,512)
        float2 x0 = buf[SW(p       )];
        float2 x1 = buf[SW(p +  512)];
        float2 x2 = buf[SW(p + 1024)];
        float2 x3 = buf[SW(p + 1536)];
        float2 e  = cadd(x0, x2), o  = cadd(x1, x3);
        float2 em = csub(x0, x2), om = cmuli(csub(x1, x3));
        float2 y0 = cadd(e, o);          // n = p
        float2 y1 = cadd(em, om);        // n = p + 512
        float2 y2 = csub(e, o);          // n = p + 1024
        float2 y3 = csub(em, om);        // n = p + 1536
        float2 w;
        w = g_win[p       ]; fr[p       ] = make_float2(y0.x*w.x, y0.y*w.y);
        w = g_win[p +  512]; fr[p +  512] = make_float2(y1.x*w.x, y1.y*w.y);
        w = g_win[p + 1024]; fr[p + 1024] = make_float2(y2.x*w.x, y2.y*w.y);
        w = g_win[p + 1536]; fr[p + 1536] = make_float2(y3.x*w.x, y3.y*w.y);
    }
}

// ---------------- gather overlap-add, segment-structured, float4 -------------
__global__ void __launch_bounds__(256) ola_kernel(const float* __restrict__ wsi,
                                                  float* __restrict__ out, int outlen)
{
    int s = blockIdx.x;                // 1024-sample output segment
    int b = blockIdx.y;
    int r = threadIdx.x << 2;          // 0..1020, float4 per thread
    int j = (s << 10) + r;
    if (j >= outlen) return;
    int p   = j + MH;                  // position in padded signal (skip N/2)
    int seg = p >> 10;                 // = s + 2
    const float* frbase = (const float*)g_frames + (size_t)b * TFR * NFFT;

    float4 acc = make_float4(0.f, 0.f, 0.f, 0.f);
    #pragma unroll
    for (int d = 0; d < 4; d++) {
        int t = seg - d;
        if (t >= 0 && t < TFR) {
            const float4 v = *(const float4*)(frbase + (size_t)t * NFFT + r + (d << 10));
            acc.x += v.x; acc.y += v.y; acc.z += v.z; acc.w += v.w;
        }
    }
    float4 wv = *(const float4*)(wsi + p);
    float4 o;
    o.x = acc.x * wv.x; o.y = acc.y * wv.y;
    o.z = acc.z * wv.z; o.w = acc.w * wv.w;
    *(float4*)(out + (size_t)b * outlen + j) = o;
}

// ---------------- launch -----------------------------------------------------
extern "C" void kernel_launch(void* const* d_in, const int* in_sizes, int n_in,
                              void* d_out, int out_size)
{
    const float* re  = (const float*)d_in[0];
    const float* im  = (const float*)d_in[1];
    // d_in[2] = inverse_basis (unused: replaced analytically by the iFFT)
    const float* wsi = (const float*)d_in[3];
    float* out = (float*)d_out;
    int outlen = out_size / BATCH;     // 352800

    dim3 tgrid((CH + 31) / 32, (TFR + 31) / 32, BATCH);
    transpose_kernel<<<tgrid, dim3(32, 32)>>>(re, im);

    ifft_kernel<<<NFRAMES, 256>>>();

    ola_kernel<<<dim3((outlen + 1023) / 1024, BATCH), 256>>>(wsi, out, outlen);
}

// round 4
// speedup vs baseline: 2.2075x; 1.2957x over previous
#include <cuda_runtime.h>

#define BATCH   8
#define CH      2049          // N/2+1 spectrum bins
#define CHP     2064          // padded row: 2064*8 = 16512 B = 129*128 (aligned)
#define TFR     345           // frames
#define NFFT    4096
#define MH      2048          // NFFT/2 = complex FFT size
#define HOP     1024
#define NFRAMES (BATCH*TFR)   // 2760

// ---------------- scratch (device globals; no allocations) ----------------
__device__ float2 g_spec[NFRAMES * CHP];    // [frame][k] = (Re, Im), padded rows
__device__ float2 g_frames[NFRAMES * MH];   // [frame][m] = (x[2m], x[2m+1])
__device__ float2 g_twN[MH];                // e^{+2*pi*i*k/4096}
__device__ float2 g_win[MH];                // (hann[2m], hann[2m+1])

// smem bank swizzle (float2 index granularity; 16 float2 = 128B row)
#define SW(p) ((p) ^ (((p) >> 4) & 15))

__device__ __forceinline__ float2 cmul(float2 a, float2 b) {
    return make_float2(a.x*b.x - a.y*b.y, a.x*b.y + a.y*b.x);
}
__device__ __forceinline__ float2 cadd(float2 a, float2 b){ return make_float2(a.x+b.x, a.y+b.y); }
__device__ __forceinline__ float2 csub(float2 a, float2 b){ return make_float2(a.x-b.x, a.y-b.y); }
__device__ __forceinline__ float2 cmuli(float2 a){ return make_float2(-a.y, a.x); }   // i*a

// ---------------- transpose [B, CH, T] -> g_spec, fused fp32 table init -----
// 32x32 tile, 32x8 threads, 4 rows per thread (MLP 8 across re+im).
__global__ void __launch_bounds__(256) transpose_kernel(const float* __restrict__ re,
                                                        const float* __restrict__ im)
{
    __shared__ float sr[32][33];
    __shared__ float si[32][33];
    int b  = blockIdx.z;
    int k0 = blockIdx.x << 5, t0 = blockIdx.y << 5;
    int tx = threadIdx.x, ty = threadIdx.y;   // ty in [0,8)

    // fused table init: first 8 (x,0,0) blocks cover 2048 ids, fp32 sinpif/cospif
    if (blockIdx.y == 0 && blockIdx.z == 0 && blockIdx.x < 8) {
        int gid = (blockIdx.x << 8) + (ty << 5) + tx;   // 0..2047
        float a = (float)gid * (1.0f / 2048.0f);        // angle in units of pi
        float s, c;
        sincospif(a, &s, &c);
        g_twN[gid] = make_float2(c, s);                 // e^{+i*2pi*gid/4096}
        float c0, c1;
        c0 = cospif((float)(2*gid)     * (1.0f / 2048.0f));
        c1 = cospif((float)(2*gid + 1) * (1.0f / 2048.0f));
        g_win[gid] = make_float2(0.5f - 0.5f*c0, 0.5f - 0.5f*c1);
    }

    const float* rb = re + (size_t)b * CH * TFR;
    const float* ib = im + (size_t)b * CH * TFR;
    int t = t0 + tx;
    bool tok = (t < TFR);
    #pragma unroll
    for (int j = 0; j < 4; j++) {
        int k = k0 + ty + (j << 3);
        if (k < CH && tok) {
            sr[ty + (j << 3)][tx] = rb[k * TFR + t];
            si[ty + (j << 3)][tx] = ib[k * TFR + t];
        }
    }
    __syncthreads();
    int ko = k0 + tx;
    bool kok = (ko < CH);
    #pragma unroll
    for (int j = 0; j < 4; j++) {
        int to = t0 + ty + (j << 3);
        if (kok && to < TFR)
            g_spec[((size_t)b * TFR + to) * CHP + ko] =
                make_float2(sr[tx][ty + (j << 3)], si[tx][ty + (j << 3)]);
    }
}

// ---------------- in-place radix-8 Stockham DIF pass (inverse, e^{+}) -------
__device__ __forceinline__ void radix8_pass_ip(float2* __restrict__ buf,
                                               const float2* __restrict__ tws,
                                               int tid, int m)
{
    int i  = tid & (m - 1);
    int jm = tid - i;

    float2 x0 = buf[SW(tid        )];
    float2 x1 = buf[SW(tid +  256)];
    float2 x2 = buf[SW(tid +  512)];
    float2 x3 = buf[SW(tid +  768)];
    float2 x4 = buf[SW(tid + 1024)];
    float2 x5 = buf[SW(tid + 1280)];
    float2 x6 = buf[SW(tid + 1536)];
    float2 x7 = buf[SW(tid + 1792)];
    float2 w1 = tws[jm];
    __syncthreads();

    float2 ta = cadd(x0, x4), tb = csub(x0, x4);
    float2 tc = cadd(x2, x6), td = cmuli(csub(x2, x6));
    float2 E0 = cadd(ta, tc), E1 = cadd(tb, td);
    float2 E2 = csub(ta, tc), E3 = csub(tb, td);
    float2 sa = cadd(x1, x5), sb = csub(x1, x5);
    float2 sc = cadd(x3, x7), sd = cmuli(csub(x3, x7));
    float2 O0 = cadd(sa, sc), O1 = cadd(sb, sd);
    float2 O2 = csub(sa, sc), O3 = csub(sb, sd);
    const float R = 0.70710678118654752440f;
    O1 = make_float2(R*(O1.x - O1.y), R*(O1.x + O1.y));
    O2 = cmuli(O2);
    O3 = make_float2(R*(-O3.x - O3.y), R*(O3.x - O3.y));

    float2 y0 = cadd(E0, O0), y4 = csub(E0, O0);
    float2 y1 = cadd(E1, O1), y5 = csub(E1, O1);
    float2 y2 = cadd(E2, O2), y6 = csub(E2, O2);
    float2 y3 = cadd(E3, O3), y7 = csub(E3, O3);

    float2 w2 = cmul(w1, w1);
    float2 w3 = cmul(w2, w1);
    float2 w4 = cmul(w2, w2);
    float2 w5 = cmul(w3, w2);
    float2 w6 = cmul(w3, w3);
    float2 w7 = cmul(w4, w3);

    int base = tid + 7 * jm;          // = 8*jm + i
    buf[SW(base      )] = y0;
    buf[SW(base +   m)] = cmul(y1, w1);
    buf[SW(base + 2*m)] = cmul(y2, w2);
    buf[SW(base + 3*m)] = cmul(y3, w3);
    buf[SW(base + 4*m)] = cmul(y4, w4);
    buf[SW(base + 5*m)] = cmul(y5, w5);
    buf[SW(base + 6*m)] = cmul(y6, w6);
    buf[SW(base + 7*m)] = cmul(y7, w7);
    __syncthreads();
}

// ---------------- per-frame inverse real FFT (size 4096) ---------------------
__global__ void __launch_bounds__(256) ifft_kernel()
{
    __shared__ float2 buf[MH];     // single in-place buffer (16 KB)
    __shared__ float2 tws[256];    // W_2048^r, r in [0,256)

    int f   = blockIdx.x;
    int tid = threadIdx.x;
    const float2* __restrict__ X = g_spec + (size_t)f * CHP;

    tws[tid] = g_twN[2 * tid];

    const float sc = 1.0f / 256.0f;
    #pragma unroll
    for (int j = 0; j < 8; j++) {
        int k = tid + (j << 8);
        float2 Xk = X[k];
        float2 Xc = X[MH - k];
        if (k == 0) { Xk.y = 0.f; Xc.y = 0.f; }
        float ex = sc * (Xk.x + Xc.x);
        float ey = sc * (Xk.y - Xc.y);
        float dx = sc * (Xk.x - Xc.x);
        float dy = sc * (Xk.y + Xc.y);
        float2 w = g_twN[k];
        float ox = dx * w.x - dy * w.y;
        float oy = dx * w.y + dy * w.x;
        buf[SW(k)] = make_float2(ex - oy, ey + ox);
    }
    __syncthreads();

    radix8_pass_ip(buf, tws, tid, 1);
    radix8_pass_ip(buf, tws, tid, 8);
    radix8_pass_ip(buf, tws, tid, 64);

    // final radix-4 pass (m=512, jm=0 -> twiddle-free) fused with window+store
    float2* __restrict__ fr = g_frames + (size_t)f * MH;
    #pragma unroll
    for (int j = 0; j < 2; j++) {
        int p = tid + (j << 8);                     // butterfly index in [0,512)
        float2 x0 = buf[SW(p       )];
        float2 x1 = buf[SW(p +  512)];
        float2 x2 = buf[SW(p + 1024)];
        float2 x3 = buf[SW(p + 1536)];
        float2 e  = cadd(x0, x2), o  = cadd(x1, x3);
        float2 em = csub(x0, x2), om = cmuli(csub(x1, x3));
        float2 y0 = cadd(e, o);
        float2 y1 = cadd(em, om);
        float2 y2 = csub(e, o);
        float2 y3 = csub(em, om);
        float2 w;
        w = g_win[p       ]; fr[p       ] = make_float2(y0.x*w.x, y0.y*w.y);
        w = g_win[p +  512]; fr[p +  512] = make_float2(y1.x*w.x, y1.y*w.y);
        w = g_win[p + 1024]; fr[p + 1024] = make_float2(y2.x*w.x, y2.y*w.y);
        w = g_win[p + 1536]; fr[p + 1536] = make_float2(y3.x*w.x, y3.y*w.y);
    }
}

// ---------------- gather overlap-add, segment-structured, float4 -------------
__global__ void __launch_bounds__(256) ola_kernel(const float* __restrict__ wsi,
                                                  float* __restrict__ out, int outlen)
{
    int s = blockIdx.x;                // 1024-sample output segment
    int b = blockIdx.y;
    int r = threadIdx.x << 2;          // 0..1020, float4 per thread
    int j = (s << 10) + r;
    if (j >= outlen) return;
    int p   = j + MH;                  // position in padded signal (skip N/2)
    int seg = p >> 10;                 // = s + 2
    const float* frbase = (const float*)g_frames + (size_t)b * TFR * NFFT;

    float4 acc = make_float4(0.f, 0.f, 0.f, 0.f);
    #pragma unroll
    for (int d = 0; d < 4; d++) {
        int t = seg - d;
        if (t >= 0 && t < TFR) {
            const float4 v = *(const float4*)(frbase + (size_t)t * NFFT + r + (d << 10));
            acc.x += v.x; acc.y += v.y; acc.z += v.z; acc.w += v.w;
        }
    }
    float4 wv = *(const float4*)(wsi + p);
    float4 o;
    o.x = acc.x * wv.x; o.y = acc.y * wv.y;
    o.z = acc.z * wv.z; o.w = acc.w * wv.w;
    *(float4*)(out + (size_t)b * outlen + j) = o;
}

// ---------------- launch -----------------------------------------------------
extern "C" void kernel_launch(void* const* d_in, const int* in_sizes, int n_in,
                              void* d_out, int out_size)
{
    const float* re  = (const float*)d_in[0];
    const float* im  = (const float*)d_in[1];
    // d_in[2] = inverse_basis (unused: replaced analytically by the iFFT)
    const float* wsi = (const float*)d_in[3];
    float* out = (float*)d_out;
    int outlen = out_size / BATCH;     // 352800

    dim3 tgrid((CH + 31) / 32, (TFR + 31) / 32, BATCH);
    transpose_kernel<<<tgrid, dim3(32, 8)>>>(re, im);

    ifft_kernel<<<NFRAMES, 256>>>();

    ola_kernel<<<dim3((outlen + 1023) / 1024, BATCH), 256>>>(wsi, out, outlen);
}

// round 5
// speedup vs baseline: 2.2118x; 1.0019x over previous
#include <cuda_runtime.h>
#include <cuda_fp16.h>

#define BATCH   8
#define CH      2049          // N/2+1 spectrum bins
#define CHP     2064          // padded row: 2064*8 B, 128B-aligned rows
#define TFR     345           // frames
#define NFFT    4096
#define MH      2048          // NFFT/2 = complex FFT size
#define HOP     1024
#define NFRAMES (BATCH*TFR)   // 2760

// ---------------- scratch (device globals; no allocations) ----------------
__device__ float2 g_spec[NFRAMES * CHP];    // [frame][k] = (Re, Im), padded rows
__device__ __half g_frames[NFRAMES * NFFT]; // [frame][n] windowed time samples (fp16)
__device__ float2 g_twN[MH];                // e^{+2*pi*i*k/4096}
__device__ float2 g_win[MH];                // (hann[2m], hann[2m+1])

// smem bank swizzle (float2 index granularity; 16 float2 = 128B row)
#define SW(p) ((p) ^ (((p) >> 4) & 15))

__device__ __forceinline__ float2 cmul(float2 a, float2 b) {
    return make_float2(a.x*b.x - a.y*b.y, a.x*b.y + a.y*b.x);
}
__device__ __forceinline__ float2 cadd(float2 a, float2 b){ return make_float2(a.x+b.x, a.y+b.y); }
__device__ __forceinline__ float2 csub(float2 a, float2 b){ return make_float2(a.x-b.x, a.y-b.y); }
__device__ __forceinline__ float2 cmuli(float2 a){ return make_float2(-a.y, a.x); }   // i*a

// ---------------- transpose [B, CH, T] -> g_spec, fused fp32 table init -----
// 32k x 64t tile, 32x8 threads, 8 elems/thread/array (16 loads in flight).
__global__ void __launch_bounds__(256) transpose_kernel(const float* __restrict__ re,
                                                        const float* __restrict__ im)
{
    __shared__ float sr[32][65];
    __shared__ float si[32][65];
    int b  = blockIdx.z;
    int k0 = blockIdx.x << 5, t0 = blockIdx.y << 6;
    int tx = threadIdx.x, ty = threadIdx.y;   // ty in [0,8)

    // fused table init: first 8 (x,0,0) blocks cover 2048 ids, fp32 sinpi/cospi
    if (blockIdx.y == 0 && blockIdx.z == 0 && blockIdx.x < 8) {
        int gid = (blockIdx.x << 8) + (ty << 5) + tx;   // 0..2047
        float a = (float)gid * (1.0f / 2048.0f);        // angle in units of pi
        float s, c;
        sincospif(a, &s, &c);
        g_twN[gid] = make_float2(c, s);                 // e^{+i*2pi*gid/4096}
        float c0 = cospif((float)(2*gid)     * (1.0f / 2048.0f));
        float c1 = cospif((float)(2*gid + 1) * (1.0f / 2048.0f));
        g_win[gid] = make_float2(0.5f - 0.5f*c0, 0.5f - 0.5f*c1);
    }

    const float* rb = re + (size_t)b * CH * TFR;
    const float* ib = im + (size_t)b * CH * TFR;
    #pragma unroll
    for (int u = 0; u < 2; u++) {
        int t = t0 + tx + (u << 5);
        bool tok = (t < TFR);
        #pragma unroll
        for (int j = 0; j < 4; j++) {
            int kl = ty + (j << 3);
            int k  = k0 + kl;
            if (k < CH && tok) {
                sr[kl][tx + (u << 5)] = rb[k * TFR + t];
                si[kl][tx + (u << 5)] = ib[k * TFR + t];
            }
        }
    }
    __syncthreads();
    int ko = k0 + tx;
    bool kok = (ko < CH);
    #pragma unroll
    for (int u = 0; u < 2; u++) {
        #pragma unroll
        for (int j = 0; j < 4; j++) {
            int tl = ty + (j << 3) + (u << 5);
            int to = t0 + tl;
            if (kok && to < TFR)
                g_spec[((size_t)b * TFR + to) * CHP + ko] =
                    make_float2(sr[tx][tl], si[tx][tl]);
        }
    }
}

// ---------------- in-place radix-8 Stockham DIF pass (inverse, e^{+}) -------
__device__ __forceinline__ void radix8_pass_ip(float2* __restrict__ buf,
                                               const float2* __restrict__ tws,
                                               int tid, int m)
{
    int i  = tid & (m - 1);
    int jm = tid - i;

    float2 x0 = buf[SW(tid        )];
    float2 x1 = buf[SW(tid +  256)];
    float2 x2 = buf[SW(tid +  512)];
    float2 x3 = buf[SW(tid +  768)];
    float2 x4 = buf[SW(tid + 1024)];
    float2 x5 = buf[SW(tid + 1280)];
    float2 x6 = buf[SW(tid + 1536)];
    float2 x7 = buf[SW(tid + 1792)];
    float2 w1 = tws[jm];
    __syncthreads();

    float2 ta = cadd(x0, x4), tb = csub(x0, x4);
    float2 tc = cadd(x2, x6), td = cmuli(csub(x2, x6));
    float2 E0 = cadd(ta, tc), E1 = cadd(tb, td);
    float2 E2 = csub(ta, tc), E3 = csub(tb, td);
    float2 sa = cadd(x1, x5), sb = csub(x1, x5);
    float2 sc = cadd(x3, x7), sd = cmuli(csub(x3, x7));
    float2 O0 = cadd(sa, sc), O1 = cadd(sb, sd);
    float2 O2 = csub(sa, sc), O3 = csub(sb, sd);
    const float R = 0.70710678118654752440f;
    O1 = make_float2(R*(O1.x - O1.y), R*(O1.x + O1.y));
    O2 = cmuli(O2);
    O3 = make_float2(R*(-O3.x - O3.y), R*(O3.x - O3.y));

    float2 y0 = cadd(E0, O0), y4 = csub(E0, O0);
    float2 y1 = cadd(E1, O1), y5 = csub(E1, O1);
    float2 y2 = cadd(E2, O2), y6 = csub(E2, O2);
    float2 y3 = cadd(E3, O3), y7 = csub(E3, O3);

    float2 w2 = cmul(w1, w1);
    float2 w3 = cmul(w2, w1);
    float2 w4 = cmul(w2, w2);
    float2 w5 = cmul(w3, w2);
    float2 w6 = cmul(w3, w3);
    float2 w7 = cmul(w4, w3);

    int base = tid + 7 * jm;          // = 8*jm + i
    buf[SW(base      )] = y0;
    buf[SW(base +   m)] = cmul(y1, w1);
    buf[SW(base + 2*m)] = cmul(y2, w2);
    buf[SW(base + 3*m)] = cmul(y3, w3);
    buf[SW(base + 4*m)] = cmul(y4, w4);
    buf[SW(base + 5*m)] = cmul(y5, w5);
    buf[SW(base + 6*m)] = cmul(y6, w6);
    buf[SW(base + 7*m)] = cmul(y7, w7);
    __syncthreads();
}

// ---------------- per-frame inverse real FFT (size 4096) ---------------------
__global__ void __launch_bounds__(256) ifft_kernel()
{
    __shared__ float2 buf[MH];     // single in-place buffer (16 KB)
    __shared__ float2 tws[256];    // W_2048^r, r in [0,256)

    int f   = blockIdx.x;
    int tid = threadIdx.x;
    const float2* __restrict__ X = g_spec + (size_t)f * CHP;

    tws[tid] = g_twN[2 * tid];

    const float sc = 1.0f / 256.0f;
    #pragma unroll
    for (int j = 0; j < 8; j++) {
        int k = tid + (j << 8);
        float2 Xk = X[k];
        float2 Xc = X[MH - k];
        if (k == 0) { Xk.y = 0.f; Xc.y = 0.f; }
        float ex = sc * (Xk.x + Xc.x);
        float ey = sc * (Xk.y - Xc.y);
        float dx = sc * (Xk.x - Xc.x);
        float dy = sc * (Xk.y + Xc.y);
        float2 w = g_twN[k];
        float ox = dx * w.x - dy * w.y;
        float oy = dx * w.y + dy * w.x;
        buf[SW(k)] = make_float2(ex - oy, ey + ox);
    }
    __syncthreads();

    radix8_pass_ip(buf, tws, tid, 1);
    radix8_pass_ip(buf, tws, tid, 8);
    radix8_pass_ip(buf, tws, tid, 64);

    // final radix-4 pass (m=512, jm=0 -> twiddle-free) fused with window + fp16 store
    __half2* __restrict__ fr = (__half2*)(g_frames + (size_t)f * NFFT);
    #pragma unroll
    for (int j = 0; j < 2; j++) {
        int p = tid + (j << 8);                     // butterfly index in [0,512)
        float2 x0 = buf[SW(p       )];
        float2 x1 = buf[SW(p +  512)];
        float2 x2 = buf[SW(p + 1024)];
        float2 x3 = buf[SW(p + 1536)];
        float2 e  = cadd(x0, x2), o  = cadd(x1, x3);
        float2 em = csub(x0, x2), om = cmuli(csub(x1, x3));
        float2 y0 = cadd(e, o);
        float2 y1 = cadd(em, om);
        float2 y2 = csub(e, o);
        float2 y3 = csub(em, om);
        float2 w;
        w = g_win[p       ]; fr[p       ] = __floats2half2_rn(y0.x*w.x, y0.y*w.y);
        w = g_win[p +  512]; fr[p +  512] = __floats2half2_rn(y1.x*w.x, y1.y*w.y);
        w = g_win[p + 1024]; fr[p + 1024] = __floats2half2_rn(y2.x*w.x, y2.y*w.y);
        w = g_win[p + 1536]; fr[p + 1536] = __floats2half2_rn(y3.x*w.x, y3.y*w.y);
    }
}

// ---------------- gather overlap-add (fp16 frames -> fp32), 8 samples/thread -
__global__ void __launch_bounds__(128) ola_kernel(const float* __restrict__ wsi,
                                                  float* __restrict__ out, int outlen)
{
    int s = blockIdx.x;                // 1024-sample output segment
    int b = blockIdx.y;
    int r = threadIdx.x << 3;          // 0..1016, 8 halves (16B) per thread
    int j = (s << 10) + r;
    if (j + 8 > outlen) return;        // tail is a multiple of 8 -> exact
    int p   = j + MH;                  // position in padded signal (skip N/2)
    int seg = p >> 10;                 // = s + 2
    const __half* frbase = g_frames + (size_t)b * TFR * NFFT;

    float acc[8] = {0,0,0,0,0,0,0,0};
    #pragma unroll
    for (int d = 0; d < 4; d++) {
        int t = seg - d;
        if (t >= 0 && t < TFR) {
            uint4 raw = *(const uint4*)(frbase + (size_t)t * NFFT + r + (d << 10));
            float2 v;
            v = __half22float2(*(__half2*)&raw.x); acc[0] += v.x; acc[1] += v.y;
            v = __half22float2(*(__half2*)&raw.y); acc[2] += v.x; acc[3] += v.y;
            v = __half22float2(*(__half2*)&raw.z); acc[4] += v.x; acc[5] += v.y;
            v = __half22float2(*(__half2*)&raw.w); acc[6] += v.x; acc[7] += v.y;
        }
    }
    float4 w0 = *(const float4*)(wsi + p);
    float4 w1 = *(const float4*)(wsi + p + 4);
    float* op = out + (size_t)b * outlen + j;
    *(float4*)(op)     = make_float4(acc[0]*w0.x, acc[1]*w0.y, acc[2]*w0.z, acc[3]*w0.w);
    *(float4*)(op + 4) = make_float4(acc[4]*w1.x, acc[5]*w1.y, acc[6]*w1.z, acc[7]*w1.w);
}

// ---------------- launch -----------------------------------------------------
extern "C" void kernel_launch(void* const* d_in, const int* in_sizes, int n_in,
                              void* d_out, int out_size)
{
    const float* re  = (const float*)d_in[0];
    const float* im  = (const float*)d_in[1];
    // d_in[2] = inverse_basis (unused: replaced analytically by the iFFT)
    const float* wsi = (const float*)d_in[3];
    float* out = (float*)d_out;
    int outlen = out_size / BATCH;     // 352800

    dim3 tgrid((CH + 31) / 32, (TFR + 63) / 64, BATCH);
    transpose_kernel<<<tgrid, dim3(32, 8)>>>(re, im);

    ifft_kernel<<<NFRAMES, 256>>>();

    ola_kernel<<<dim3((outlen + 1023) / 1024, BATCH), 128>>>(wsi, out, outlen);
}